// round 15
// baseline (speedup 1.0000x reference)
#include <cuda_runtime.h>
#include <cuda_fp16.h>
#include <math.h>

// ---------------- problem constants ----------------
#define LTOK 32768      // B * D*H*W
#define CDIM 192
#define NWIN 64
#define NHD  6
#define NTOK 512
#define HDD  32
#define NWH  (NWIN*NHD)   // 384

typedef unsigned int u32;
typedef __half f16;

// ---------------- device scratch (static, allocation-free) ----------------
__device__ float g_h2[LTOK * CDIM];
__device__ float g_x2[LTOK * CDIM];
__device__ float g_bias[NHD * NTOK * NTOK];
__device__ float g_pp[128 * CDIM];
__device__ float g_ca[CDIM];
// fp16 activations
__device__ f16 g_xn [LTOK * CDIM];
__device__ f16 g_ao [LTOK * CDIM];
__device__ f16 g_x2n[LTOK * CDIM];
__device__ f16 g_h1 [LTOK * 64];
__device__ f16 g_mh [(size_t)LTOK * 768];
// attention operands
__device__ f16 g_q [NWH * NTOK * HDD];   // scaled
__device__ f16 g_k [NWH * NTOK * HDD];
__device__ f16 g_vt[NWH * HDD * NTOK];   // V transposed [wh][d][tok]
// fp16 weights
__device__ f16 g_qkvw[576 * 192];
__device__ f16 g_projw[192 * 192];
__device__ f16 g_fc1w[768 * 192];
__device__ f16 g_fc2w[192 * 768];
__device__ f16 g_w1t[27 * 64 * 192];   // [kk][co][ci]
__device__ f16 g_w2t[27 * 192 * 64];

__device__ __forceinline__ float gelu_exact(float x) {
    return 0.5f * x * (1.0f + erff(x * 0.70710678118654752440f));
}
__device__ __forceinline__ u32 packh2(float a, float b) {
    __half2 t = __floats2half2_rn(a, b);
    return *(u32*)&t;
}

// ---------------- mma / ldmatrix / cp.async helpers ----------------
__device__ __forceinline__ void ldm4(u32& r0, u32& r1, u32& r2, u32& r3, const f16* p) {
    u32 addr = (u32)__cvta_generic_to_shared(p);
    asm volatile("ldmatrix.sync.aligned.m8n8.x4.shared.b16 {%0,%1,%2,%3},[%4];"
                 : "=r"(r0), "=r"(r1), "=r"(r2), "=r"(r3) : "r"(addr));
}
__device__ __forceinline__ void mma16816(float* c, const u32* a, const u32* b) {
    asm volatile(
        "mma.sync.aligned.m16n8k16.row.col.f32.f16.f16.f32 "
        "{%0,%1,%2,%3},{%4,%5,%6,%7},{%8,%9},{%0,%1,%2,%3};"
        : "+f"(c[0]), "+f"(c[1]), "+f"(c[2]), "+f"(c[3])
        : "r"(a[0]), "r"(a[1]), "r"(a[2]), "r"(a[3]), "r"(b[0]), "r"(b[1]));
}
__device__ __forceinline__ void cp16(f16* dst, const f16* src) {
    u32 d = (u32)__cvta_generic_to_shared(dst);
    asm volatile("cp.async.cg.shared.global [%0],[%1],16;" :: "r"(d), "l"(src));
}
__device__ __forceinline__ void cp16z(f16* dst, const f16* src, bool v) {
    u32 d = (u32)__cvta_generic_to_shared(dst);
    int sz = v ? 16 : 0;
    asm volatile("cp.async.cg.shared.global [%0],[%1],16,%2;" :: "r"(d), "l"(src), "r"(sz));
}
#define CP_COMMIT() asm volatile("cp.async.commit_group;")
#define CP_WAIT1()  asm volatile("cp.async.wait_group 1;")

// ---------------- LayerNorm -> fp16 ----------------
__global__ void ln_kernel(const float* __restrict__ x, const float* __restrict__ g,
                          const float* __restrict__ b, f16* __restrict__ dst) {
    int row  = blockIdx.x * blockDim.y + threadIdx.y;
    int lane = threadIdx.x;
    const float* xr = x + (size_t)row * CDIM;
    float v[6]; float s = 0.f, ss = 0.f;
#pragma unroll
    for (int i = 0; i < 6; i++) { v[i] = xr[lane + 32*i]; s += v[i]; ss += v[i]*v[i]; }
#pragma unroll
    for (int o = 16; o > 0; o >>= 1) {
        s  += __shfl_xor_sync(0xffffffffu, s, o);
        ss += __shfl_xor_sync(0xffffffffu, ss, o);
    }
    float mean = s * (1.f/192.f);
    float var  = ss * (1.f/192.f) - mean*mean;
    float rstd = rsqrtf(var + 1e-5f);
    f16* orow = dst + (size_t)row * CDIM;
#pragma unroll
    for (int i = 0; i < 6; i++) {
        int c = lane + 32*i;
        orow[c] = __float2half((v[i]-mean)*rstd*g[c] + b[c]);
    }
}

// ---------------- fused prep: weight conversions + bias gather (PDL trigger) ----------------
__global__ void prep_kernel(const float* __restrict__ qkvw, const float* __restrict__ projw,
                            const float* __restrict__ fc1w, const float* __restrict__ fc2w,
                            const float* __restrict__ c1w,  const float* __restrict__ c2w,
                            const int* __restrict__ rpi,    const float* __restrict__ rpb) {
#if __CUDA_ARCH__ >= 900
    cudaTriggerProgrammaticLaunchCompletion();
#endif
    int idx = blockIdx.x * 256 + threadIdx.x;
    if (idx < 110592) { g_qkvw[idx] = __float2half(qkvw[idx]); return; }
    idx -= 110592;
    if (idx < 36864)  { g_projw[idx] = __float2half(projw[idx]); return; }
    idx -= 36864;
    if (idx < 147456) { g_fc1w[idx] = __float2half(fc1w[idx]); return; }
    idx -= 147456;
    if (idx < 147456) { g_fc2w[idx] = __float2half(fc2w[idx]); return; }
    idx -= 147456;
    if (idx < 331776) {
        int co = idx / (192*27), ci = (idx / 27) % 192, kk = idx % 27;
        g_w1t[((size_t)kk*64 + co)*192 + ci] = __float2half(c1w[idx]); return;
    }
    idx -= 331776;
    if (idx < 331776) {
        int co = idx / (64*27), ci = (idx / 27) % 64, kk = idx % 27;
        g_w2t[((size_t)kk*192 + co)*64 + ci] = __float2half(c2w[idx]); return;
    }
    idx -= 331776;
    if (idx < NHD * NTOK * NTOK) {
        int h  = idx / (NTOK*NTOK);
        int nm = idx % (NTOK*NTOK);
        g_bias[idx] = rpb[rpi[nm]*NHD + h];
    }
}

// ---------------- epilogue dispatch ----------------
// EPI: 1 qkv-scatter, 2 proj+residual, 3 fc1 gelu->f16, 4 final add
template<int EPI>
__device__ __forceinline__ void epi_store(int m, int n, float v,
                                          float* __restrict__ out,
                                          const float* __restrict__ aux0) {
    if (EPI == 1) {
        int which = n / 192, c = n % 192;
        int head = c >> 5, hd = c & 31;
        int d = m >> 12, h = (m >> 6) & 63, w = m & 63;
        int wi = ((h >> 3) << 3) | (w >> 3);
        int nt = (d << 6) | ((h & 7) << 3) | (w & 7);
        int wh = wi*NHD + head;
        if (which == 0)
            g_q[((size_t)wh*NTOK + nt)*HDD + hd] = __float2half(v * 0.17677669529663687f);
        else if (which == 1)
            g_k[((size_t)wh*NTOK + nt)*HDD + hd] = __float2half(v);
        else
            g_vt[((size_t)wh*HDD + hd)*NTOK + nt] = __float2half(v);
    } else if (EPI == 2) {
        int wi = m >> 9, nt = m & 511;
        int d = nt >> 6;
        int h = ((wi >> 3) << 3) | ((nt >> 3) & 7);
        int w = ((wi & 7) << 3) | (nt & 7);
        size_t l = ((size_t)d << 12) | (h << 6) | w;
        size_t o = l*CDIM + n;
        g_x2[o] = aux0[o] + v + g_h2[o] * g_ca[n] * 0.01f;
    } else if (EPI == 3) {
        g_mh[(size_t)m * 768 + n] = __float2half(gelu_exact(v));
    } else { // EPI == 4
        out[(size_t)m*CDIM + n] = g_x2[(size_t)m*CDIM + n] + v;
    }
}

// ---------------- fp16 tensor-core GEMM, M128xN64, K32, 3-stage cp.async ----------------
template<int EPI>
__global__ __launch_bounds__(256)
void gemm_f16(const f16* __restrict__ A, const f16* __restrict__ B,
              const float* __restrict__ bias, float* __restrict__ out,
              int Kc, const float* __restrict__ aux0) {
    __shared__ __align__(16) f16 As[3][128][40];
    __shared__ __align__(16) f16 Bs[3][64][40];
    const int m0 = blockIdx.x * 128;
    const int n0 = blockIdx.y * 64;
    const int tid = threadIdx.x;
    const int lane = tid & 31, warp = tid >> 5;
    const int warp_m = warp & 3, warp_n = warp >> 2;

    const int arow = tid >> 1, acolv = (tid & 1) * 16;
    const int brow = tid >> 2, bcolv = (tid & 3) * 8;
    const f16* aptr = A + (size_t)(m0 + arow) * Kc + acolv;
    const f16* bptr = B + (size_t)(n0 + brow) * Kc + bcolv;

    const int a_r  = warp_m*32 + (lane & 7) + ((lane >> 3) & 1) * 8;
    const int a_c8 = (lane >> 4) * 8;
    const int b_r  = warp_n*32 + (lane >> 4) * 8 + (lane & 7);
    const int b_c8 = ((lane >> 3) & 1) * 8;

    float acc[2][4][4];
#pragma unroll
    for (int i = 0; i < 2; i++)
#pragma unroll
        for (int j = 0; j < 4; j++)
#pragma unroll
            for (int t = 0; t < 4; t++) acc[i][j][t] = 0.f;

    const int nk = Kc >> 5;
    auto issue = [&](int ks) {
        if (ks < nk) {
            int s = ks % 3;
            cp16(&As[s][arow][acolv],     aptr + ks*32);
            cp16(&As[s][arow][acolv + 8], aptr + ks*32 + 8);
            cp16(&Bs[s][brow][bcolv],     bptr + ks*32);
        }
        CP_COMMIT();
    };
    issue(0); issue(1);

    for (int ks = 0; ks < nk; ks++) {
        CP_WAIT1();
        __syncthreads();
        issue(ks + 2);
        const int s = ks % 3;
#pragma unroll
        for (int half = 0; half < 2; half++) {
            u32 afr[2][4], bfr[4][2];
#pragma unroll
            for (int mt = 0; mt < 2; mt++)
                ldm4(afr[mt][0], afr[mt][1], afr[mt][2], afr[mt][3],
                     &As[s][a_r + mt*16][half*16 + a_c8]);
#pragma unroll
            for (int np = 0; np < 2; np++)
                ldm4(bfr[2*np][0], bfr[2*np][1], bfr[2*np+1][0], bfr[2*np+1][1],
                     &Bs[s][b_r + np*16][half*16 + b_c8]);
#pragma unroll
            for (int mt = 0; mt < 2; mt++)
#pragma unroll
                for (int nt = 0; nt < 4; nt++)
                    mma16816(acc[mt][nt], afr[mt], bfr[nt]);
        }
    }
#pragma unroll
    for (int mt = 0; mt < 2; mt++) {
        int mrow = m0 + warp_m*32 + mt*16 + (lane >> 2);
#pragma unroll
        for (int nt = 0; nt < 4; nt++) {
            int ncol = n0 + warp_n*32 + nt*8 + 2*(lane & 3);
            epi_store<EPI>(mrow,     ncol,     acc[mt][nt][0] + bias[ncol],   out, aux0);
            epi_store<EPI>(mrow,     ncol + 1, acc[mt][nt][1] + bias[ncol+1], out, aux0);
            epi_store<EPI>(mrow + 8, ncol,     acc[mt][nt][2] + bias[ncol],   out, aux0);
            epi_store<EPI>(mrow + 8, ncol + 1, acc[mt][nt][3] + bias[ncol+1], out, aux0);
        }
    }
}

// ---------------- fp16 tensor-core 3x3x3 conv, M128xN64, K32, NT n-tiles per block ----------------
// PDL trigger at block start. Grid = 256 blocks (single wave) so the trigger fires
// immediately and the PDL successor overlaps the WHOLE conv, not just its tail.
// CEPI: 0 = gelu -> g_h1 f16 (COUT=64), 1 = plain fp32 -> g_h2
template<int CEPI, int NT>
__global__ __launch_bounds__(256)
void conv_f16(const f16* __restrict__ Ain, const f16* __restrict__ Wt,
              const float* __restrict__ bias, int Kc, int COUT) {
#if __CUDA_ARCH__ >= 900
    cudaTriggerProgrammaticLaunchCompletion();
#endif
    __shared__ __align__(16) f16 As[3][128][40];
    __shared__ __align__(16) f16 Bs[3][64][40];
    const int l0 = blockIdx.x * 128;
    const int tid = threadIdx.x;
    const int lane = tid & 31, warp = tid >> 5;
    const int warp_m = warp & 3, warp_n = warp >> 2;

    const int arow = tid >> 1, acolv = (tid & 1) * 16;
    const int l = l0 + arow;
    const int d = l >> 12, hh = (l >> 6) & 63, ww = l & 63;
    const int brow = tid >> 2, bcolv = (tid & 3) * 8;

    const int a_r  = warp_m*32 + (lane & 7) + ((lane >> 3) & 1) * 8;
    const int a_c8 = (lane >> 4) * 8;
    const int b_r  = warp_n*32 + (lane >> 4) * 8 + (lane & 7);
    const int b_c8 = ((lane >> 3) & 1) * 8;

    const int nchunk = Kc >> 5;
    const int nks = 27 * nchunk;

    for (int ny = 0; ny < NT; ny++) {
        const int n0 = ny * 64;
        if (ny > 0) __syncthreads();   // protect smem reuse across tiles

        float acc[2][4][4];
#pragma unroll
        for (int i = 0; i < 2; i++)
#pragma unroll
            for (int j = 0; j < 4; j++)
#pragma unroll
                for (int t = 0; t < 4; t++) acc[i][j][t] = 0.f;

        auto issue = [&](int ks) {
            if (ks < nks) {
                int s = ks % 3;
                int kk = ks / nchunk, c0 = (ks % nchunk) * 32;
                int dd = kk/9 - 1, dh = (kk/3)%3 - 1, dw = kk%3 - 1;
                bool valid = ((unsigned)(d+dd) < 8u) && ((unsigned)(hh+dh) < 64u) && ((unsigned)(ww+dw) < 64u);
                const f16* p = valid ? (Ain + (size_t)(l + dd*4096 + dh*64 + dw) * Kc + c0 + acolv) : Ain;
                cp16z(&As[s][arow][acolv],     p,     valid);
                cp16z(&As[s][arow][acolv + 8], p + 8, valid);
                cp16(&Bs[s][brow][bcolv],
                     Wt + ((size_t)kk*COUT + n0 + brow) * Kc + c0 + bcolv);
            }
            CP_COMMIT();
        };
        issue(0); issue(1);

        for (int ks = 0; ks < nks; ks++) {
            CP_WAIT1();
            __syncthreads();
            issue(ks + 2);
            const int s = ks % 3;
#pragma unroll
            for (int half = 0; half < 2; half++) {
                u32 afr[2][4], bfr[4][2];
#pragma unroll
                for (int mt = 0; mt < 2; mt++)
                    ldm4(afr[mt][0], afr[mt][1], afr[mt][2], afr[mt][3],
                         &As[s][a_r + mt*16][half*16 + a_c8]);
#pragma unroll
                for (int np = 0; np < 2; np++)
                    ldm4(bfr[2*np][0], bfr[2*np][1], bfr[2*np+1][0], bfr[2*np+1][1],
                         &Bs[s][b_r + np*16][half*16 + b_c8]);
#pragma unroll
                for (int mt = 0; mt < 2; mt++)
#pragma unroll
                    for (int nt = 0; nt < 4; nt++)
                        mma16816(acc[mt][nt], afr[mt], bfr[nt]);
            }
        }
#pragma unroll
        for (int mt = 0; mt < 2; mt++) {
            int row = warp_m*32 + mt*16 + (lane >> 2);
#pragma unroll
            for (int nt = 0; nt < 4; nt++) {
                int co = n0 + warp_n*32 + nt*8 + 2*(lane & 3);
#pragma unroll
                for (int q = 0; q < 4; q++) {
                    int tok = l0 + row + (q >> 1) * 8;
                    int c   = co + (q & 1);
                    float v = acc[mt][nt][q] + bias[c];
                    if (CEPI == 0) g_h1[(size_t)tok * 64 + c] = __float2half(gelu_exact(v));
                    else           g_h2[(size_t)tok * CDIM + c] = v;
                }
            }
        }
    }
}

// ---------------- global avg pool (stage 1) ----------------
__global__ void pool_kernel(const float* __restrict__ h2, float* __restrict__ partial) {
    int b = blockIdx.x, c = threadIdx.x;
    float s = 0.f;
    const float* base = h2 + (size_t)b * 256 * CDIM + c;
    for (int r = 0; r < 256; r++) s += base[(size_t)r * CDIM];
    partial[b*CDIM + c] = s;
}

// ---------------- channel attention (stage 2) ----------------
__global__ void ca_kernel(const float* __restrict__ partial,
                          const float* __restrict__ ca1w, const float* __restrict__ ca1b,
                          const float* __restrict__ ca2w, const float* __restrict__ ca2b) {
    __shared__ float pooled[CDIM];
    __shared__ float t6[6];
    int c = threadIdx.x;
    float s = 0.f;
    for (int b = 0; b < 128; b++) s += partial[b*CDIM + c];
    pooled[c] = s * (1.f/32768.f);
    __syncthreads();
    if (c < 6) {
        float a = ca1b[c];
        for (int i = 0; i < CDIM; i++) a += pooled[i] * ca1w[c*CDIM + i];
        t6[c] = fmaxf(a, 0.f);
    }
    __syncthreads();
    float a = ca2b[c];
#pragma unroll
    for (int j = 0; j < 6; j++) a += t6[j] * ca2w[c*6 + j];
    g_ca[c] = 1.f / (1.f + __expf(-a));
}

// ---------------- flash attention: no-max softmax, streamed PV, low regs ----------------
#define QS_SZ  (128*40)
#define KS_SZ  (128*40)
#define VS_SZ  (32*136)
__global__ __launch_bounds__(256, 2)
void fa_kernel() {
    extern __shared__ __align__(16) f16 sm[];
    f16* Qs = sm;                        // [128][40]
    f16* Ks = Qs + QS_SZ;                // [3][128][40]
    f16* Vs = Ks + 3*KS_SZ;              // [3][32][136]

    const int wh = blockIdx.y, qt = blockIdx.x;
    const int wi = wh / NHD, hh = wh % NHD;
    const int tid = threadIdx.x, lane = tid & 31, warp = tid >> 5;

    const f16* qg = g_q  + ((size_t)wh*NTOK + qt*128) * HDD;
    const f16* kg = g_k  + (size_t)wh*NTOK*HDD;
    const f16* vg = g_vt + (size_t)wh*HDD*NTOK;

    for (int c = tid; c < 512; c += 256)
        cp16(&Qs[(c>>2)*40 + (c&3)*8], qg + (c>>2)*HDD + (c&3)*8);
    auto issue_tile = [&](int j) {
        if (j < 4) {
            f16* ks = Ks + (j % 3) * KS_SZ;
            f16* vs = Vs + (j % 3) * VS_SZ;
            const f16* kt = kg + j*128*HDD;
            for (int c = tid; c < 512; c += 256) {
                cp16(&ks[(c>>2)*40 + (c&3)*8], kt + (c>>2)*HDD + (c&3)*8);
                int dv = c >> 4, ov = (c & 15) * 8;
                cp16(&vs[dv*136 + ov], vg + dv*NTOK + j*128 + ov);
            }
        }
        CP_COMMIT();
    };
    issue_tile(0);
    issue_tile(1);

    const int a_r  = warp*16 + (lane & 7) + ((lane >> 3) & 1) * 8;
    const int a_c8 = (lane >> 4) * 8;
    const int b_rr = (lane >> 4) * 8 + (lane & 7);
    const int b_c8 = ((lane >> 3) & 1) * 8;

    u32 qfr[2][4];
    float o[4][4];
#pragma unroll
    for (int i = 0; i < 4; i++)
#pragma unroll
        for (int j = 0; j < 4; j++) o[i][j] = 0.f;
    float l0 = 0.f, l1 = 0.f;

    const int nq = qt*128 + warp*16 + (lane >> 2);
    const float* bias_base = g_bias + ((size_t)hh*NTOK + nq)*NTOK + 2*(lane & 3);

    for (int j = 0; j < 4; j++) {
        CP_WAIT1();
        __syncthreads();
        if (j == 0) {
#pragma unroll
            for (int ks = 0; ks < 2; ks++)
                ldm4(qfr[ks][0], qfr[ks][1], qfr[ks][2], qfr[ks][3],
                     &Qs[a_r*40 + ks*16 + a_c8]);
        }
        issue_tile(j + 2);
        const f16* ks_s = Ks + (j % 3) * KS_SZ;
        const f16* vs_s = Vs + (j % 3) * VS_SZ;
        const float* bp = bias_base + j*128;

#pragma unroll
        for (int kt = 0; kt < 8; kt++) {
            float sf[2][4];
#pragma unroll
            for (int q = 0; q < 4; q++) { sf[0][q] = 0.f; sf[1][q] = 0.f; }
#pragma unroll
            for (int ks = 0; ks < 2; ks++) {
                u32 b[4];
                ldm4(b[0], b[1], b[2], b[3],
                     &ks_s[(kt*16 + b_rr)*40 + ks*16 + b_c8]);
                mma16816(sf[0], qfr[ks], b);
                mma16816(sf[1], qfr[ks], b + 2);
            }
            float2 a0 = *(const float2*)(bp + 2*kt*8);
            float2 a1 = *(const float2*)(bp + 8*NTOK + 2*kt*8);
            float2 c0 = *(const float2*)(bp + (2*kt+1)*8);
            float2 c1 = *(const float2*)(bp + 8*NTOK + (2*kt+1)*8);
            sf[0][0] = __expf(sf[0][0] + a0.x);
            sf[0][1] = __expf(sf[0][1] + a0.y);
            sf[0][2] = __expf(sf[0][2] + a1.x);
            sf[0][3] = __expf(sf[0][3] + a1.y);
            sf[1][0] = __expf(sf[1][0] + c0.x);
            sf[1][1] = __expf(sf[1][1] + c0.y);
            sf[1][2] = __expf(sf[1][2] + c1.x);
            sf[1][3] = __expf(sf[1][3] + c1.y);
            l0 += sf[0][0] + sf[0][1] + sf[1][0] + sf[1][1];
            l1 += sf[0][2] + sf[0][3] + sf[1][2] + sf[1][3];
            u32 pfr[4];
            pfr[0] = packh2(sf[0][0], sf[0][1]);
            pfr[1] = packh2(sf[0][2], sf[0][3]);
            pfr[2] = packh2(sf[1][0], sf[1][1]);
            pfr[3] = packh2(sf[1][2], sf[1][3]);
            u32 vf[8];
            ldm4(vf[0], vf[1], vf[2], vf[3], &vs_s[b_rr*136 + kt*16 + b_c8]);
            ldm4(vf[4], vf[5], vf[6], vf[7], &vs_s[(16 + b_rr)*136 + kt*16 + b_c8]);
#pragma unroll
            for (int dt = 0; dt < 4; dt++)
                mma16816(o[dt], pfr, &vf[2*dt]);
        }
    }
    l0 += __shfl_xor_sync(0xffffffffu, l0, 1);
    l0 += __shfl_xor_sync(0xffffffffu, l0, 2);
    l1 += __shfl_xor_sync(0xffffffffu, l1, 1);
    l1 += __shfl_xor_sync(0xffffffffu, l1, 2);

    float il0 = 1.f / l0, il1 = 1.f / l1;
    int row = wi*NTOK + qt*128 + warp*16 + (lane >> 2);
    f16* dst0 = g_ao + (size_t)row * CDIM;
    f16* dst1 = dst0 + (size_t)8 * CDIM;
#pragma unroll
    for (int dt = 0; dt < 4; dt++) {
        int c = hh*HDD + dt*8 + 2*(lane & 3);
        dst0[c]     = __float2half(o[dt][0]*il0);
        dst0[c + 1] = __float2half(o[dt][1]*il0);
        dst1[c]     = __float2half(o[dt][2]*il1);
        dst1[c + 1] = __float2half(o[dt][3]*il1);
    }
}

// ---------------- launch ----------------
extern "C" void kernel_launch(void* const* d_in, const int* in_sizes, int n_in,
                              void* d_out, int out_size) {
    const float* x     = (const float*)d_in[0];
    const float* n1g   = (const float*)d_in[1];
    const float* n1b   = (const float*)d_in[2];
    const float* qkvw  = (const float*)d_in[3];
    const float* qkvb  = (const float*)d_in[4];
    const float* rpb   = (const float*)d_in[5];
    const float* projw = (const float*)d_in[6];
    const float* projb = (const float*)d_in[7];
    const float* c1w   = (const float*)d_in[8];
    const float* c1b   = (const float*)d_in[9];
    const float* c2w   = (const float*)d_in[10];
    const float* c2b   = (const float*)d_in[11];
    const float* ca1w  = (const float*)d_in[12];
    const float* ca1b  = (const float*)d_in[13];
    const float* ca2w  = (const float*)d_in[14];
    const float* ca2b  = (const float*)d_in[15];
    const float* n2g   = (const float*)d_in[16];
    const float* n2b   = (const float*)d_in[17];
    const float* fc1w  = (const float*)d_in[18];
    const float* fc1b  = (const float*)d_in[19];
    const float* fc2w  = (const float*)d_in[20];
    const float* fc2b  = (const float*)d_in[21];
    const int*   rpi   = (const int*)d_in[22];
    float* out = (float*)d_out;

    f16 *p_xn, *p_ao, *p_x2n, *p_h1, *p_mh;
    f16 *p_qkvw, *p_projw, *p_fc1w, *p_fc2w, *p_w1t, *p_w2t;
    float *p_h2, *p_x2, *p_pp;
    cudaGetSymbolAddress((void**)&p_xn,    g_xn);
    cudaGetSymbolAddress((void**)&p_ao,    g_ao);
    cudaGetSymbolAddress((void**)&p_x2n,   g_x2n);
    cudaGetSymbolAddress((void**)&p_h1,    g_h1);
    cudaGetSymbolAddress((void**)&p_mh,    g_mh);
    cudaGetSymbolAddress((void**)&p_qkvw,  g_qkvw);
    cudaGetSymbolAddress((void**)&p_projw, g_projw);
    cudaGetSymbolAddress((void**)&p_fc1w,  g_fc1w);
    cudaGetSymbolAddress((void**)&p_fc2w,  g_fc2w);
    cudaGetSymbolAddress((void**)&p_w1t,   g_w1t);
    cudaGetSymbolAddress((void**)&p_w2t,   g_w2t);
    cudaGetSymbolAddress((void**)&p_h2,    g_h2);
    cudaGetSymbolAddress((void**)&p_x2,    g_x2);
    cudaGetSymbolAddress((void**)&p_pp,    g_pp);

    const int fa_smem = (QS_SZ + 3*KS_SZ + 3*VS_SZ) * (int)sizeof(f16);
    cudaFuncSetAttribute(fa_kernel, cudaFuncAttributeMaxDynamicSharedMemorySize, fa_smem);

    cudaLaunchAttribute pdl[1];
    pdl[0].id = cudaLaunchAttributeProgrammaticStreamSerialization;
    pdl[0].val.programmaticStreamSerializationAllowed = 1;

    // 1) fused weight conversions + bias gather (trigger at start)
    prep_kernel<<<(2678784 + 255)/256, 256>>>(qkvw, projw, fc1w, fc2w, c1w, c2w, rpi, rpb);
    // 2) LN1 overlaps prep (fully independent: reads x, writes g_xn)
    {
        cudaLaunchConfig_t cfg = {};
        cfg.gridDim = dim3(4096); cfg.blockDim = dim3(32, 8);
        cfg.attrs = pdl; cfg.numAttrs = 1;
        cudaLaunchKernelEx(&cfg, ln_kernel, x, n1g, n1b, p_xn);
    }
    // 3) conv1 (256 blocks = 1 wave; triggers at start) ...
    conv_f16<0, 1><<<256, 256>>>(p_xn, p_w1t, c1b, 192, 64);
    // ... QKV overlaps conv1 entirely
    {
        cudaLaunchConfig_t cfg = {};
        cfg.gridDim = dim3(256, 9); cfg.blockDim = dim3(256);
        cfg.attrs = pdl; cfg.numAttrs = 1;
        cudaLaunchKernelEx(&cfg, gemm_f16<1>, p_xn, (const f16*)p_qkvw, qkvb,
                           (float*)nullptr, 192, (const float*)nullptr);
    }
    // 4) conv2 as 256 blocks x 3 internal N-tiles (1 wave; triggers at start) ...
    conv_f16<1, 3><<<256, 256>>>(p_h1, p_w2t, c2b, 64, 192);
    // ... FA overlaps conv2 entirely
    {
        cudaLaunchConfig_t cfg = {};
        cfg.gridDim = dim3(4, NWH); cfg.blockDim = dim3(256);
        cfg.dynamicSmemBytes = fa_smem;
        cfg.attrs = pdl; cfg.numAttrs = 1;
        cudaLaunchKernelEx(&cfg, fa_kernel);
    }
    // 5) channel attention tail (normal launches: wait full prefix)
    pool_kernel<<<128, CDIM>>>(p_h2, p_pp);
    ca_kernel<<<1, CDIM>>>(p_pp, ca1w, ca1b, ca2w, ca2b);
    // 6) proj + window reverse + residual + conv*0.01 -> g_x2
    gemm_f16<2><<<dim3(256, 3), 256>>>(p_ao, p_projw, projb, nullptr, 192, x);
    // 7) LN2 + MLP
    ln_kernel<<<4096, dim3(32, 8)>>>(p_x2, n2g, n2b, p_x2n);
    gemm_f16<3><<<dim3(256, 12), 256>>>(p_x2n, p_fc1w, fc1b, nullptr, 192, nullptr);
    gemm_f16<4><<<dim3(256, 3), 256>>>(p_mh, p_fc2w, fc2b, out, 768, nullptr);
}

// round 16
// speedup vs baseline: 1.0169x; 1.0169x over previous
#include <cuda_runtime.h>
#include <cuda_fp16.h>
#include <math.h>

// ---------------- problem constants ----------------
#define LTOK 32768      // B * D*H*W
#define CDIM 192
#define NWIN 64
#define NHD  6
#define NTOK 512
#define HDD  32
#define NWH  (NWIN*NHD)   // 384

typedef unsigned int u32;
typedef __half f16;

// ---------------- device scratch (static, allocation-free) ----------------
__device__ float g_h2[LTOK * CDIM];
__device__ float g_x2[LTOK * CDIM];
__device__ float g_bias[NHD * NTOK * NTOK];
__device__ float g_pp[128 * CDIM];
__device__ float g_ca[CDIM];
// fp16 activations
__device__ f16 g_xn [LTOK * CDIM];
__device__ f16 g_ao [LTOK * CDIM];
__device__ f16 g_x2n[LTOK * CDIM];
__device__ f16 g_h1 [LTOK * 64];
__device__ f16 g_mh [(size_t)LTOK * 768];
// attention operands
__device__ f16 g_q [NWH * NTOK * HDD];   // scaled
__device__ f16 g_k [NWH * NTOK * HDD];
__device__ f16 g_vt[NWH * HDD * NTOK];   // V transposed [wh][d][tok]
// fp16 weights
__device__ f16 g_qkvw[576 * 192];
__device__ f16 g_projw[192 * 192];
__device__ f16 g_fc1w[768 * 192];
__device__ f16 g_fc2w[192 * 768];
__device__ f16 g_w1t[27 * 64 * 192];   // [kk][co][ci]
__device__ f16 g_w2t[27 * 192 * 64];

__device__ __forceinline__ float gelu_exact(float x) {
    return 0.5f * x * (1.0f + erff(x * 0.70710678118654752440f));
}
__device__ __forceinline__ u32 packh2(float a, float b) {
    __half2 t = __floats2half2_rn(a, b);
    return *(u32*)&t;
}

// ---------------- mma / ldmatrix / cp.async helpers ----------------
__device__ __forceinline__ void ldm4(u32& r0, u32& r1, u32& r2, u32& r3, const f16* p) {
    u32 addr = (u32)__cvta_generic_to_shared(p);
    asm volatile("ldmatrix.sync.aligned.m8n8.x4.shared.b16 {%0,%1,%2,%3},[%4];"
                 : "=r"(r0), "=r"(r1), "=r"(r2), "=r"(r3) : "r"(addr));
}
__device__ __forceinline__ void mma16816(float* c, const u32* a, const u32* b) {
    asm volatile(
        "mma.sync.aligned.m16n8k16.row.col.f32.f16.f16.f32 "
        "{%0,%1,%2,%3},{%4,%5,%6,%7},{%8,%9},{%0,%1,%2,%3};"
        : "+f"(c[0]), "+f"(c[1]), "+f"(c[2]), "+f"(c[3])
        : "r"(a[0]), "r"(a[1]), "r"(a[2]), "r"(a[3]), "r"(b[0]), "r"(b[1]));
}
__device__ __forceinline__ void cp16(f16* dst, const f16* src) {
    u32 d = (u32)__cvta_generic_to_shared(dst);
    asm volatile("cp.async.cg.shared.global [%0],[%1],16;" :: "r"(d), "l"(src));
}
__device__ __forceinline__ void cp16z(f16* dst, const f16* src, bool v) {
    u32 d = (u32)__cvta_generic_to_shared(dst);
    int sz = v ? 16 : 0;
    asm volatile("cp.async.cg.shared.global [%0],[%1],16,%2;" :: "r"(d), "l"(src), "r"(sz));
}
#define CP_COMMIT() asm volatile("cp.async.commit_group;")
#define CP_WAIT1()  asm volatile("cp.async.wait_group 1;")

// ---------------- LayerNorm -> fp16 ----------------
__global__ void ln_kernel(const float* __restrict__ x, const float* __restrict__ g,
                          const float* __restrict__ b, f16* __restrict__ dst) {
    int row  = blockIdx.x * blockDim.y + threadIdx.y;
    int lane = threadIdx.x;
    const float* xr = x + (size_t)row * CDIM;
    float v[6]; float s = 0.f, ss = 0.f;
#pragma unroll
    for (int i = 0; i < 6; i++) { v[i] = xr[lane + 32*i]; s += v[i]; ss += v[i]*v[i]; }
#pragma unroll
    for (int o = 16; o > 0; o >>= 1) {
        s  += __shfl_xor_sync(0xffffffffu, s, o);
        ss += __shfl_xor_sync(0xffffffffu, ss, o);
    }
    float mean = s * (1.f/192.f);
    float var  = ss * (1.f/192.f) - mean*mean;
    float rstd = rsqrtf(var + 1e-5f);
    f16* orow = dst + (size_t)row * CDIM;
#pragma unroll
    for (int i = 0; i < 6; i++) {
        int c = lane + 32*i;
        orow[c] = __float2half((v[i]-mean)*rstd*g[c] + b[c]);
    }
}

// ---------------- fused prep: weight conversions + bias gather (PDL trigger) ----------------
__global__ void prep_kernel(const float* __restrict__ qkvw, const float* __restrict__ projw,
                            const float* __restrict__ fc1w, const float* __restrict__ fc2w,
                            const float* __restrict__ c1w,  const float* __restrict__ c2w,
                            const int* __restrict__ rpi,    const float* __restrict__ rpb) {
#if __CUDA_ARCH__ >= 900
    cudaTriggerProgrammaticLaunchCompletion();
#endif
    int idx = blockIdx.x * 256 + threadIdx.x;
    if (idx < 110592) { g_qkvw[idx] = __float2half(qkvw[idx]); return; }
    idx -= 110592;
    if (idx < 36864)  { g_projw[idx] = __float2half(projw[idx]); return; }
    idx -= 36864;
    if (idx < 147456) { g_fc1w[idx] = __float2half(fc1w[idx]); return; }
    idx -= 147456;
    if (idx < 147456) { g_fc2w[idx] = __float2half(fc2w[idx]); return; }
    idx -= 147456;
    if (idx < 331776) {
        int co = idx / (192*27), ci = (idx / 27) % 192, kk = idx % 27;
        g_w1t[((size_t)kk*64 + co)*192 + ci] = __float2half(c1w[idx]); return;
    }
    idx -= 331776;
    if (idx < 331776) {
        int co = idx / (64*27), ci = (idx / 27) % 64, kk = idx % 27;
        g_w2t[((size_t)kk*192 + co)*64 + ci] = __float2half(c2w[idx]); return;
    }
    idx -= 331776;
    if (idx < NHD * NTOK * NTOK) {
        int h  = idx / (NTOK*NTOK);
        int nm = idx % (NTOK*NTOK);
        g_bias[idx] = rpb[rpi[nm]*NHD + h];
    }
}

// ---------------- epilogue dispatch ----------------
// EPI: 1 qkv-scatter, 2 proj+residual, 3 fc1 gelu->f16, 4 final add
template<int EPI>
__device__ __forceinline__ void epi_store(int m, int n, float v,
                                          float* __restrict__ out,
                                          const float* __restrict__ aux0) {
    if (EPI == 1) {
        int which = n / 192, c = n % 192;
        int head = c >> 5, hd = c & 31;
        int d = m >> 12, h = (m >> 6) & 63, w = m & 63;
        int wi = ((h >> 3) << 3) | (w >> 3);
        int nt = (d << 6) | ((h & 7) << 3) | (w & 7);
        int wh = wi*NHD + head;
        if (which == 0)
            g_q[((size_t)wh*NTOK + nt)*HDD + hd] = __float2half(v * 0.17677669529663687f);
        else if (which == 1)
            g_k[((size_t)wh*NTOK + nt)*HDD + hd] = __float2half(v);
        else
            g_vt[((size_t)wh*HDD + hd)*NTOK + nt] = __float2half(v);
    } else if (EPI == 2) {
        int wi = m >> 9, nt = m & 511;
        int d = nt >> 6;
        int h = ((wi >> 3) << 3) | ((nt >> 3) & 7);
        int w = ((wi & 7) << 3) | (nt & 7);
        size_t l = ((size_t)d << 12) | (h << 6) | w;
        size_t o = l*CDIM + n;
        g_x2[o] = aux0[o] + v + g_h2[o] * g_ca[n] * 0.01f;
    } else if (EPI == 3) {
        g_mh[(size_t)m * 768 + n] = __float2half(gelu_exact(v));
    } else { // EPI == 4
        out[(size_t)m*CDIM + n] = g_x2[(size_t)m*CDIM + n] + v;
    }
}

// ---------------- fp16 tensor-core GEMM, M128xN64, K32, 3-stage cp.async ----------------
template<int EPI>
__global__ __launch_bounds__(256)
void gemm_f16(const f16* __restrict__ A, const f16* __restrict__ B,
              const float* __restrict__ bias, float* __restrict__ out,
              int Kc, const float* __restrict__ aux0) {
    __shared__ __align__(16) f16 As[3][128][40];
    __shared__ __align__(16) f16 Bs[3][64][40];
    const int m0 = blockIdx.x * 128;
    const int n0 = blockIdx.y * 64;
    const int tid = threadIdx.x;
    const int lane = tid & 31, warp = tid >> 5;
    const int warp_m = warp & 3, warp_n = warp >> 2;

    const int arow = tid >> 1, acolv = (tid & 1) * 16;
    const int brow = tid >> 2, bcolv = (tid & 3) * 8;
    const f16* aptr = A + (size_t)(m0 + arow) * Kc + acolv;
    const f16* bptr = B + (size_t)(n0 + brow) * Kc + bcolv;

    const int a_r  = warp_m*32 + (lane & 7) + ((lane >> 3) & 1) * 8;
    const int a_c8 = (lane >> 4) * 8;
    const int b_r  = warp_n*32 + (lane >> 4) * 8 + (lane & 7);
    const int b_c8 = ((lane >> 3) & 1) * 8;

    float acc[2][4][4];
#pragma unroll
    for (int i = 0; i < 2; i++)
#pragma unroll
        for (int j = 0; j < 4; j++)
#pragma unroll
            for (int t = 0; t < 4; t++) acc[i][j][t] = 0.f;

    const int nk = Kc >> 5;
    auto issue = [&](int ks) {
        if (ks < nk) {
            int s = ks % 3;
            cp16(&As[s][arow][acolv],     aptr + ks*32);
            cp16(&As[s][arow][acolv + 8], aptr + ks*32 + 8);
            cp16(&Bs[s][brow][bcolv],     bptr + ks*32);
        }
        CP_COMMIT();
    };
    issue(0); issue(1);

    for (int ks = 0; ks < nk; ks++) {
        CP_WAIT1();
        __syncthreads();
        issue(ks + 2);
        const int s = ks % 3;
#pragma unroll
        for (int half = 0; half < 2; half++) {
            u32 afr[2][4], bfr[4][2];
#pragma unroll
            for (int mt = 0; mt < 2; mt++)
                ldm4(afr[mt][0], afr[mt][1], afr[mt][2], afr[mt][3],
                     &As[s][a_r + mt*16][half*16 + a_c8]);
#pragma unroll
            for (int np = 0; np < 2; np++)
                ldm4(bfr[2*np][0], bfr[2*np][1], bfr[2*np+1][0], bfr[2*np+1][1],
                     &Bs[s][b_r + np*16][half*16 + b_c8]);
#pragma unroll
            for (int mt = 0; mt < 2; mt++)
#pragma unroll
                for (int nt = 0; nt < 4; nt++)
                    mma16816(acc[mt][nt], afr[mt], bfr[nt]);
        }
    }
#pragma unroll
    for (int mt = 0; mt < 2; mt++) {
        int mrow = m0 + warp_m*32 + mt*16 + (lane >> 2);
#pragma unroll
        for (int nt = 0; nt < 4; nt++) {
            int ncol = n0 + warp_n*32 + nt*8 + 2*(lane & 3);
            epi_store<EPI>(mrow,     ncol,     acc[mt][nt][0] + bias[ncol],   out, aux0);
            epi_store<EPI>(mrow,     ncol + 1, acc[mt][nt][1] + bias[ncol+1], out, aux0);
            epi_store<EPI>(mrow + 8, ncol,     acc[mt][nt][2] + bias[ncol],   out, aux0);
            epi_store<EPI>(mrow + 8, ncol + 1, acc[mt][nt][3] + bias[ncol+1], out, aux0);
        }
    }
}

// ---------------- fp16 tensor-core 3x3x3 conv, M128xN64, K32, 3-stage ----------------
// PDL trigger at block start. CEPI: 0 = gelu -> g_h1 (COUT=64), 1 = fp32 -> g_h2
template<int CEPI>
__global__ __launch_bounds__(256)
void conv_f16(const f16* __restrict__ Ain, const f16* __restrict__ Wt,
              const float* __restrict__ bias, int Kc, int COUT) {
#if __CUDA_ARCH__ >= 900
    cudaTriggerProgrammaticLaunchCompletion();
#endif
    __shared__ __align__(16) f16 As[3][128][40];
    __shared__ __align__(16) f16 Bs[3][64][40];
    const int l0 = blockIdx.x * 128;
    const int n0 = blockIdx.y * 64;
    const int tid = threadIdx.x;
    const int lane = tid & 31, warp = tid >> 5;
    const int warp_m = warp & 3, warp_n = warp >> 2;

    const int arow = tid >> 1, acolv = (tid & 1) * 16;
    const int l = l0 + arow;
    const int d = l >> 12, hh = (l >> 6) & 63, ww = l & 63;
    const int brow = tid >> 2, bcolv = (tid & 3) * 8;

    const int a_r  = warp_m*32 + (lane & 7) + ((lane >> 3) & 1) * 8;
    const int a_c8 = (lane >> 4) * 8;
    const int b_r  = warp_n*32 + (lane >> 4) * 8 + (lane & 7);
    const int b_c8 = ((lane >> 3) & 1) * 8;

    float acc[2][4][4];
#pragma unroll
    for (int i = 0; i < 2; i++)
#pragma unroll
        for (int j = 0; j < 4; j++)
#pragma unroll
            for (int t = 0; t < 4; t++) acc[i][j][t] = 0.f;

    const int nchunk = Kc >> 5;
    const int nks = 27 * nchunk;

    auto issue = [&](int ks) {
        if (ks < nks) {
            int s = ks % 3;
            int kk = ks / nchunk, c0 = (ks % nchunk) * 32;
            int dd = kk/9 - 1, dh = (kk/3)%3 - 1, dw = kk%3 - 1;
            bool valid = ((unsigned)(d+dd) < 8u) && ((unsigned)(hh+dh) < 64u) && ((unsigned)(ww+dw) < 64u);
            const f16* p = valid ? (Ain + (size_t)(l + dd*4096 + dh*64 + dw) * Kc + c0 + acolv) : Ain;
            cp16z(&As[s][arow][acolv],     p,     valid);
            cp16z(&As[s][arow][acolv + 8], p + 8, valid);
            cp16(&Bs[s][brow][bcolv],
                 Wt + ((size_t)kk*COUT + n0 + brow) * Kc + c0 + bcolv);
        }
        CP_COMMIT();
    };
    issue(0); issue(1);

    for (int ks = 0; ks < nks; ks++) {
        CP_WAIT1();
        __syncthreads();
        issue(ks + 2);
        const int s = ks % 3;
#pragma unroll
        for (int half = 0; half < 2; half++) {
            u32 afr[2][4], bfr[4][2];
#pragma unroll
            for (int mt = 0; mt < 2; mt++)
                ldm4(afr[mt][0], afr[mt][1], afr[mt][2], afr[mt][3],
                     &As[s][a_r + mt*16][half*16 + a_c8]);
#pragma unroll
            for (int np = 0; np < 2; np++)
                ldm4(bfr[2*np][0], bfr[2*np][1], bfr[2*np+1][0], bfr[2*np+1][1],
                     &Bs[s][b_r + np*16][half*16 + b_c8]);
#pragma unroll
            for (int mt = 0; mt < 2; mt++)
#pragma unroll
                for (int nt = 0; nt < 4; nt++)
                    mma16816(acc[mt][nt], afr[mt], bfr[nt]);
        }
    }
#pragma unroll
    for (int mt = 0; mt < 2; mt++) {
        int row = warp_m*32 + mt*16 + (lane >> 2);
#pragma unroll
        for (int nt = 0; nt < 4; nt++) {
            int co = n0 + warp_n*32 + nt*8 + 2*(lane & 3);
#pragma unroll
            for (int q = 0; q < 4; q++) {
                int tok = l0 + row + (q >> 1) * 8;
                int c   = co + (q & 1);
                float v = acc[mt][nt][q] + bias[c];
                if (CEPI == 0) g_h1[(size_t)tok * 64 + c] = __float2half(gelu_exact(v));
                else           g_h2[(size_t)tok * CDIM + c] = v;
            }
        }
    }
}

// ---------------- global avg pool (stage 1) ----------------
__global__ void pool_kernel(const float* __restrict__ h2, float* __restrict__ partial) {
    int b = blockIdx.x, c = threadIdx.x;
    float s = 0.f;
    const float* base = h2 + (size_t)b * 256 * CDIM + c;
    for (int r = 0; r < 256; r++) s += base[(size_t)r * CDIM];
    partial[b*CDIM + c] = s;
}

// ---------------- channel attention (stage 2) ----------------
__global__ void ca_kernel(const float* __restrict__ partial,
                          const float* __restrict__ ca1w, const float* __restrict__ ca1b,
                          const float* __restrict__ ca2w, const float* __restrict__ ca2b) {
    __shared__ float pooled[CDIM];
    __shared__ float t6[6];
    int c = threadIdx.x;
    float s = 0.f;
    for (int b = 0; b < 128; b++) s += partial[b*CDIM + c];
    pooled[c] = s * (1.f/32768.f);
    __syncthreads();
    if (c < 6) {
        float a = ca1b[c];
        for (int i = 0; i < CDIM; i++) a += pooled[i] * ca1w[c*CDIM + i];
        t6[c] = fmaxf(a, 0.f);
    }
    __syncthreads();
    float a = ca2b[c];
#pragma unroll
    for (int j = 0; j < 6; j++) a += t6[j] * ca2w[c*6 + j];
    g_ca[c] = 1.f / (1.f + __expf(-a));
}

// ---------------- flash attention: no-max softmax, streamed PV, low regs ----------------
#define QS_SZ  (128*40)
#define KS_SZ  (128*40)
#define VS_SZ  (32*136)
__global__ __launch_bounds__(256, 2)
void fa_kernel() {
    extern __shared__ __align__(16) f16 sm[];
    f16* Qs = sm;                        // [128][40]
    f16* Ks = Qs + QS_SZ;                // [3][128][40]
    f16* Vs = Ks + 3*KS_SZ;              // [3][32][136]

    const int wh = blockIdx.y, qt = blockIdx.x;
    const int wi = wh / NHD, hh = wh % NHD;
    const int tid = threadIdx.x, lane = tid & 31, warp = tid >> 5;

    const f16* qg = g_q  + ((size_t)wh*NTOK + qt*128) * HDD;
    const f16* kg = g_k  + (size_t)wh*NTOK*HDD;
    const f16* vg = g_vt + (size_t)wh*HDD*NTOK;

    for (int c = tid; c < 512; c += 256)
        cp16(&Qs[(c>>2)*40 + (c&3)*8], qg + (c>>2)*HDD + (c&3)*8);
    auto issue_tile = [&](int j) {
        if (j < 4) {
            f16* ks = Ks + (j % 3) * KS_SZ;
            f16* vs = Vs + (j % 3) * VS_SZ;
            const f16* kt = kg + j*128*HDD;
            for (int c = tid; c < 512; c += 256) {
                cp16(&ks[(c>>2)*40 + (c&3)*8], kt + (c>>2)*HDD + (c&3)*8);
                int dv = c >> 4, ov = (c & 15) * 8;
                cp16(&vs[dv*136 + ov], vg + dv*NTOK + j*128 + ov);
            }
        }
        CP_COMMIT();
    };
    issue_tile(0);
    issue_tile(1);

    const int a_r  = warp*16 + (lane & 7) + ((lane >> 3) & 1) * 8;
    const int a_c8 = (lane >> 4) * 8;
    const int b_rr = (lane >> 4) * 8 + (lane & 7);
    const int b_c8 = ((lane >> 3) & 1) * 8;

    u32 qfr[2][4];
    float o[4][4];
#pragma unroll
    for (int i = 0; i < 4; i++)
#pragma unroll
        for (int j = 0; j < 4; j++) o[i][j] = 0.f;
    float l0 = 0.f, l1 = 0.f;

    const int nq = qt*128 + warp*16 + (lane >> 2);
    const float* bias_base = g_bias + ((size_t)hh*NTOK + nq)*NTOK + 2*(lane & 3);

    for (int j = 0; j < 4; j++) {
        CP_WAIT1();
        __syncthreads();
        if (j == 0) {
#pragma unroll
            for (int ks = 0; ks < 2; ks++)
                ldm4(qfr[ks][0], qfr[ks][1], qfr[ks][2], qfr[ks][3],
                     &Qs[a_r*40 + ks*16 + a_c8]);
        }
        issue_tile(j + 2);
        const f16* ks_s = Ks + (j % 3) * KS_SZ;
        const f16* vs_s = Vs + (j % 3) * VS_SZ;
        const float* bp = bias_base + j*128;

#pragma unroll
        for (int kt = 0; kt < 8; kt++) {
            float sf[2][4];
#pragma unroll
            for (int q = 0; q < 4; q++) { sf[0][q] = 0.f; sf[1][q] = 0.f; }
#pragma unroll
            for (int ks = 0; ks < 2; ks++) {
                u32 b[4];
                ldm4(b[0], b[1], b[2], b[3],
                     &ks_s[(kt*16 + b_rr)*40 + ks*16 + b_c8]);
                mma16816(sf[0], qfr[ks], b);
                mma16816(sf[1], qfr[ks], b + 2);
            }
            float2 a0 = *(const float2*)(bp + 2*kt*8);
            float2 a1 = *(const float2*)(bp + 8*NTOK + 2*kt*8);
            float2 c0 = *(const float2*)(bp + (2*kt+1)*8);
            float2 c1 = *(const float2*)(bp + 8*NTOK + (2*kt+1)*8);
            sf[0][0] = __expf(sf[0][0] + a0.x);
            sf[0][1] = __expf(sf[0][1] + a0.y);
            sf[0][2] = __expf(sf[0][2] + a1.x);
            sf[0][3] = __expf(sf[0][3] + a1.y);
            sf[1][0] = __expf(sf[1][0] + c0.x);
            sf[1][1] = __expf(sf[1][1] + c0.y);
            sf[1][2] = __expf(sf[1][2] + c1.x);
            sf[1][3] = __expf(sf[1][3] + c1.y);
            l0 += sf[0][0] + sf[0][1] + sf[1][0] + sf[1][1];
            l1 += sf[0][2] + sf[0][3] + sf[1][2] + sf[1][3];
            u32 pfr[4];
            pfr[0] = packh2(sf[0][0], sf[0][1]);
            pfr[1] = packh2(sf[0][2], sf[0][3]);
            pfr[2] = packh2(sf[1][0], sf[1][1]);
            pfr[3] = packh2(sf[1][2], sf[1][3]);
            u32 vf[8];
            ldm4(vf[0], vf[1], vf[2], vf[3], &vs_s[b_rr*136 + kt*16 + b_c8]);
            ldm4(vf[4], vf[5], vf[6], vf[7], &vs_s[(16 + b_rr)*136 + kt*16 + b_c8]);
#pragma unroll
            for (int dt = 0; dt < 4; dt++)
                mma16816(o[dt], pfr, &vf[2*dt]);
        }
    }
    l0 += __shfl_xor_sync(0xffffffffu, l0, 1);
    l0 += __shfl_xor_sync(0xffffffffu, l0, 2);
    l1 += __shfl_xor_sync(0xffffffffu, l1, 1);
    l1 += __shfl_xor_sync(0xffffffffu, l1, 2);

    float il0 = 1.f / l0, il1 = 1.f / l1;
    int row = wi*NTOK + qt*128 + warp*16 + (lane >> 2);
    f16* dst0 = g_ao + (size_t)row * CDIM;
    f16* dst1 = dst0 + (size_t)8 * CDIM;
#pragma unroll
    for (int dt = 0; dt < 4; dt++) {
        int c = hh*HDD + dt*8 + 2*(lane & 3);
        dst0[c]     = __float2half(o[dt][0]*il0);
        dst0[c + 1] = __float2half(o[dt][1]*il0);
        dst1[c]     = __float2half(o[dt][2]*il1);
        dst1[c + 1] = __float2half(o[dt][3]*il1);
    }
}

// ---------------- launch ----------------
extern "C" void kernel_launch(void* const* d_in, const int* in_sizes, int n_in,
                              void* d_out, int out_size) {
    const float* x     = (const float*)d_in[0];
    const float* n1g   = (const float*)d_in[1];
    const float* n1b   = (const float*)d_in[2];
    const float* qkvw  = (const float*)d_in[3];
    const float* qkvb  = (const float*)d_in[4];
    const float* rpb   = (const float*)d_in[5];
    const float* projw = (const float*)d_in[6];
    const float* projb = (const float*)d_in[7];
    const float* c1w   = (const float*)d_in[8];
    const float* c1b   = (const float*)d_in[9];
    const float* c2w   = (const float*)d_in[10];
    const float* c2b   = (const float*)d_in[11];
    const float* ca1w  = (const float*)d_in[12];
    const float* ca1b  = (const float*)d_in[13];
    const float* ca2w  = (const float*)d_in[14];
    const float* ca2b  = (const float*)d_in[15];
    const float* n2g   = (const float*)d_in[16];
    const float* n2b   = (const float*)d_in[17];
    const float* fc1w  = (const float*)d_in[18];
    const float* fc1b  = (const float*)d_in[19];
    const float* fc2w  = (const float*)d_in[20];
    const float* fc2b  = (const float*)d_in[21];
    const int*   rpi   = (const int*)d_in[22];
    float* out = (float*)d_out;

    f16 *p_xn, *p_ao, *p_x2n, *p_h1, *p_mh;
    f16 *p_qkvw, *p_projw, *p_fc1w, *p_fc2w, *p_w1t, *p_w2t;
    float *p_h2, *p_x2, *p_pp;
    cudaGetSymbolAddress((void**)&p_xn,    g_xn);
    cudaGetSymbolAddress((void**)&p_ao,    g_ao);
    cudaGetSymbolAddress((void**)&p_x2n,   g_x2n);
    cudaGetSymbolAddress((void**)&p_h1,    g_h1);
    cudaGetSymbolAddress((void**)&p_mh,    g_mh);
    cudaGetSymbolAddress((void**)&p_qkvw,  g_qkvw);
    cudaGetSymbolAddress((void**)&p_projw, g_projw);
    cudaGetSymbolAddress((void**)&p_fc1w,  g_fc1w);
    cudaGetSymbolAddress((void**)&p_fc2w,  g_fc2w);
    cudaGetSymbolAddress((void**)&p_w1t,   g_w1t);
    cudaGetSymbolAddress((void**)&p_w2t,   g_w2t);
    cudaGetSymbolAddress((void**)&p_h2,    g_h2);
    cudaGetSymbolAddress((void**)&p_x2,    g_x2);
    cudaGetSymbolAddress((void**)&p_pp,    g_pp);

    const int fa_smem = (QS_SZ + 3*KS_SZ + 3*VS_SZ) * (int)sizeof(f16);
    cudaFuncSetAttribute(fa_kernel, cudaFuncAttributeMaxDynamicSharedMemorySize, fa_smem);

    cudaLaunchAttribute pdl[1];
    pdl[0].id = cudaLaunchAttributeProgrammaticStreamSerialization;
    pdl[0].val.programmaticStreamSerializationAllowed = 1;

    // 1) fused weight conversions + bias gather (trigger at start)
    prep_kernel<<<(2678784 + 255)/256, 256>>>(qkvw, projw, fc1w, fc2w, c1w, c2w, rpi, rpb);
    // 2) LN1 overlaps prep (fully independent: reads x, writes g_xn)
    {
        cudaLaunchConfig_t cfg = {};
        cfg.gridDim = dim3(4096); cfg.blockDim = dim3(32, 8);
        cfg.attrs = pdl; cfg.numAttrs = 1;
        cudaLaunchKernelEx(&cfg, ln_kernel, x, n1g, n1b, p_xn);
    }
    // 3) conv1 (256 blocks = 1 wave; triggers at start) ...
    conv_f16<0><<<dim3(256, 1), 256>>>(p_xn, p_w1t, c1b, 192, 64);
    // ... QKV overlaps conv1 entirely (no data dep)
    {
        cudaLaunchConfig_t cfg = {};
        cfg.gridDim = dim3(256, 9); cfg.blockDim = dim3(256);
        cfg.attrs = pdl; cfg.numAttrs = 1;
        cudaLaunchKernelEx(&cfg, gemm_f16<1>, p_xn, (const f16*)p_qkvw, qkvb,
                           (float*)nullptr, 192, (const float*)nullptr);
    }
    // 4) conv2 (768 blocks; triggers at start of last wave) ...
    conv_f16<1><<<dim3(256, 3), 256>>>(p_h1, p_w2t, c2b, 64, 192);
    // ... FA overlaps conv2 tail (needs only QKV outputs + bias, complete before conv2 launched)
    {
        cudaLaunchConfig_t cfg = {};
        cfg.gridDim = dim3(4, NWH); cfg.blockDim = dim3(256);
        cfg.dynamicSmemBytes = fa_smem;
        cfg.attrs = pdl; cfg.numAttrs = 1;
        cudaLaunchKernelEx(&cfg, fa_kernel);
    }
    // 5) channel attention tail (normal launches: wait full prefix)
    pool_kernel<<<128, CDIM>>>(p_h2, p_pp);
    ca_kernel<<<1, CDIM>>>(p_pp, ca1w, ca1b, ca2w, ca2b);
    // 6) proj + window reverse + residual + conv*0.01 -> g_x2
    gemm_f16<2><<<dim3(256, 3), 256>>>(p_ao, p_projw, projb, nullptr, 192, x);
    // 7) LN2 + MLP
    ln_kernel<<<4096, dim3(32, 8)>>>(p_x2, n2g, n2b, p_x2n);
    gemm_f16<3><<<dim3(256, 12), 256>>>(p_x2n, p_fc1w, fc1b, nullptr, 192, nullptr);
    gemm_f16<4><<<dim3(256, 3), 256>>>(p_mh, p_fc2w, fc2b, out, 768, nullptr);
}